// round 11
// baseline (speedup 1.0000x reference)
#include <cuda_runtime.h>
#include <cstdint>
#include <cstddef>

// CosAttn2d: B=32, C=512, H=W=32, n_head=8, M=48  (shapes fixed by setup_inputs)
// bh = b*8 + head indexes 256 independent (batch, head) problems.
// qa = relu(q * 512^-0.25) + 1e-5 (same for k), v raw.
// coef_r[n] (n = h*32+w): r0=ch*cw, r1=ch*sw, r2=sh*cw, r3=sh*sw, angle = i*pi/96.
//
// Phase 1: ctx[k'=r*64+d][e] = sum_n coef_r[n]*ka[d,n]*v[e,n];  col 64 = ksum (v==1)
// Phase 2: out[e,n] = (sum_{k'} coef*qa * ctx[k'][e]) / (sum_{k'} coef*qa * ksum[k'])

#define HW      1024
#define DH      64
#define NBH     256
#define FREQ    0.0327249234748937f   // pi/96
#define DNORM   0.2102241038134286f   // 512^-0.25
#define EPS     1e-5f
#define CTX_LD  68                    // padded row (64 e + 1 ksum + pad for float4)

__device__ float g_ctx[NBH * 256 * CTX_LD];   // 17.8 MB scratch

// ---------------- Phase 1: ctx = K'^T V (one block per bh) ----------------
__global__ __launch_bounds__(256, 2)
void p1_kernel(const float* __restrict__ K, const float* __restrict__ V) {
    __shared__ float ks[64][65];   // [d][n], +1 pad -> bank = (d+n)%32
    __shared__ float vs[64][65];   // [e][n]
    __shared__ float cs[4][64];    // coef per r for current n-chunk

    const int bh = blockIdx.x;
    const int t  = threadIdx.x;
    const float* kb = K + (size_t)bh * (DH * HW);
    const float* vb = V + (size_t)bh * (DH * HW);

    const int ty = t >> 3;         // 0..31
    const int tx = t & 7;          // 0..7
    const int r  = ty >> 3;        // 0..3   (uniform per warp)
    const int dl = ty & 7;         // d = dl + 8*j  (lane-strided: conflict-free)
    // e = tx + 8*i (lane-strided: conflict-free)

    float acc[8][8];
    float ksa[8];
#pragma unroll
    for (int j = 0; j < 8; j++) {
        ksa[j] = 0.f;
#pragma unroll
        for (int i = 0; i < 8; i++) acc[j][i] = 0.f;
    }

    const int lr = t >> 4;           // load row base 0..15
    const int lc = (t & 15) << 2;    // load col 0..60

    for (int chunk = 0; chunk < 16; chunk++) {
        const int n0 = chunk << 6;
        __syncthreads();
#pragma unroll
        for (int it = 0; it < 4; it++) {
            const int row = lr + (it << 4);
            float4 kv = *(const float4*)(kb + row * HW + n0 + lc);
            ks[row][lc + 0] = fmaxf(kv.x * DNORM, 0.f) + EPS;
            ks[row][lc + 1] = fmaxf(kv.y * DNORM, 0.f) + EPS;
            ks[row][lc + 2] = fmaxf(kv.z * DNORM, 0.f) + EPS;
            ks[row][lc + 3] = fmaxf(kv.w * DNORM, 0.f) + EPS;
            float4 vv = *(const float4*)(vb + row * HW + n0 + lc);
            vs[row][lc + 0] = vv.x;
            vs[row][lc + 1] = vv.y;
            vs[row][lc + 2] = vv.z;
            vs[row][lc + 3] = vv.w;
        }
        if (t < 64) {
            const int n = n0 + t;
            float ch, sh, cw, sw;
            __sincosf((float)(n >> 5) * FREQ, &sh, &ch);
            __sincosf((float)(n & 31) * FREQ, &sw, &cw);
            cs[0][t] = ch * cw;
            cs[1][t] = ch * sw;
            cs[2][t] = sh * cw;
            cs[3][t] = sh * sw;
        }
        __syncthreads();
#pragma unroll 2
        for (int n = 0; n < 64; n++) {
            const float cf = cs[r][n];
            float a[8], bv[8];
#pragma unroll
            for (int j = 0; j < 8; j++) a[j] = ks[dl + (j << 3)][n] * cf;
#pragma unroll
            for (int i = 0; i < 8; i++) bv[i] = vs[tx + (i << 3)][n];
#pragma unroll
            for (int j = 0; j < 8; j++) {
                ksa[j] += a[j];
#pragma unroll
                for (int i = 0; i < 8; i++) acc[j][i] += a[j] * bv[i];
            }
        }
    }

    float* go = g_ctx + (size_t)bh * 256 * CTX_LD;
#pragma unroll
    for (int j = 0; j < 8; j++) {
        const int row = (r << 6) + dl + (j << 3);
#pragma unroll
        for (int i = 0; i < 8; i++)
            go[row * CTX_LD + tx + (i << 3)] = acc[j][i];
        if (tx == 0) go[row * CTX_LD + 64] = ksa[j];   // ksum column
    }
}

// ---------------- Phase 2: out = (Q' ctx) / D  (grid: 8 n-chunks x 256 bh) ----------------
__global__ __launch_bounds__(256, 2)
void p2_kernel(const float* __restrict__ Q, float* __restrict__ O) {
    __shared__ float qs[64][128];  // [d][n-chunk], float4-friendly, conflict-free

    const int bh = blockIdx.y;
    const int n0 = blockIdx.x << 7;       // 128-n chunk
    const int t  = threadIdx.x;
    const int te = t >> 5;                // 0..7 : e = te*8 + i  (warp-uniform)
    const int tn = t & 31;                // n = n0 + tn*4 + jj

    const float* qb  = Q + (size_t)bh * (DH * HW);
    float*       ob  = O + (size_t)bh * (DH * HW);
    const float* ctx = g_ctx + (size_t)bh * 256 * CTX_LD;

#pragma unroll
    for (int it = 0; it < 8; it++) {
        const int row = te + (it << 3);
        float4 qv = *(const float4*)(qb + row * HW + n0 + (tn << 2));
        float4 s;
        s.x = fmaxf(qv.x * DNORM, 0.f) + EPS;
        s.y = fmaxf(qv.y * DNORM, 0.f) + EPS;
        s.z = fmaxf(qv.z * DNORM, 0.f) + EPS;
        s.w = fmaxf(qv.w * DNORM, 0.f) + EPS;
        *(float4*)&qs[row][tn << 2] = s;
    }
    __syncthreads();

    float cf[4][4];
#pragma unroll
    for (int jj = 0; jj < 4; jj++) {
        const int n = n0 + (tn << 2) + jj;
        float ch, sh, cw, sw;
        __sincosf((float)(n >> 5) * FREQ, &sh, &ch);
        __sincosf((float)(n & 31) * FREQ, &sw, &cw);
        cf[0][jj] = ch * cw;
        cf[1][jj] = ch * sw;
        cf[2][jj] = sh * cw;
        cf[3][jj] = sh * sw;
    }

    float acc[8][4];
    float Da[4] = {0.f, 0.f, 0.f, 0.f};
#pragma unroll
    for (int i = 0; i < 8; i++)
#pragma unroll
        for (int jj = 0; jj < 4; jj++) acc[i][jj] = 0.f;

#pragma unroll
    for (int r = 0; r < 4; r++) {
        const float c0f = cf[r][0], c1f = cf[r][1], c2f = cf[r][2], c3f = cf[r][3];
        const float* crow = ctx + (size_t)(r << 6) * CTX_LD;
#pragma unroll 4
        for (int d = 0; d < 64; d++) {
            float4 a4 = *(const float4*)&qs[(r << 6) ? ((r << 6) + d - (r << 6)) : d][tn << 2]; // d row
            // (index is just d; written plainly below to avoid confusion)
            a4 = *(const float4*)&qs[d][tn << 2];
            const float ap0 = a4.x * c0f;
            const float ap1 = a4.y * c1f;
            const float ap2 = a4.z * c2f;
            const float ap3 = a4.w * c3f;
            const float4 cA = *(const float4*)(crow + (te << 3));
            const float4 cB = *(const float4*)(crow + (te << 3) + 4);
            const float ksv = crow[64];
            const float cc[8] = {cA.x, cA.y, cA.z, cA.w, cB.x, cB.y, cB.z, cB.w};
#pragma unroll
            for (int i = 0; i < 8; i++) {
                acc[i][0] += cc[i] * ap0;
                acc[i][1] += cc[i] * ap1;
                acc[i][2] += cc[i] * ap2;
                acc[i][3] += cc[i] * ap3;
            }
            Da[0] += ksv * ap0;
            Da[1] += ksv * ap1;
            Da[2] += ksv * ap2;
            Da[3] += ksv * ap3;
            crow += CTX_LD;
        }
    }

    float rin[4];
#pragma unroll
    for (int jj = 0; jj < 4; jj++) rin[jj] = 1.0f / Da[jj];
#pragma unroll
    for (int i = 0; i < 8; i++) {
        float4 o;
        o.x = acc[i][0] * rin[0];
        o.y = acc[i][1] * rin[1];
        o.z = acc[i][2] * rin[2];
        o.w = acc[i][3] * rin[3];
        *(float4*)(ob + (size_t)((te << 3) + i) * HW + n0 + (tn << 2)) = o;
    }
}

extern "C" void kernel_launch(void* const* d_in, const int* in_sizes, int n_in,
                              void* d_out, int out_size) {
    (void)in_sizes; (void)n_in; (void)out_size;
    const float* q = (const float*)d_in[0];
    const float* k = (const float*)d_in[1];
    const float* v = (const float*)d_in[2];
    float* o = (float*)d_out;

    p1_kernel<<<NBH, 256>>>(k, v);
    p2_kernel<<<dim3(8, NBH), 256>>>(q, o);
}

// round 12
// speedup vs baseline: 1.0046x; 1.0046x over previous
#include <cuda_runtime.h>
#include <cstdint>
#include <cstddef>

// CosAttn2d: B=32, C=512, H=W=32, n_head=8, M=48  (shapes fixed by setup_inputs)
// bh = b*8 + head indexes 256 independent (batch, head) problems.
// qa = relu(q * 512^-0.25) + 1e-5 (same for k), v raw.
// coef_r[n] (n = h*32+w): r0=ch*cw, r1=ch*sw, r2=sh*cw, r3=sh*sw, angle = i*pi/96.
//
// Phase 1: ctx[k'=r*64+d][e] = sum_n coef_r[n]*ka[d,n]*v[e,n];  col 64 = ksum (v==1)
// Phase 2: out[e,n] = (sum_{k'} coef*qa * ctx[k'][e]) / (sum_{k'} coef*qa * ksum[k'])

#define HW      1024
#define DH      64
#define NBH     256
#define FREQ    0.0327249234748937f   // pi/96
#define DNORM   0.2102241038134286f   // 512^-0.25
#define EPS     1e-5f
#define CTX_LD  68                    // padded row (64 e + 1 ksum + pad for float4)

__device__ float g_ctx[NBH * 256 * CTX_LD];   // 17.8 MB scratch

// ---------------- Phase 1: ctx = K'^T V (one block per bh) ----------------
__global__ __launch_bounds__(256, 2)
void p1_kernel(const float* __restrict__ K, const float* __restrict__ V) {
    __shared__ float ks[64][65];   // [d][n], +1 pad -> bank = (d+n)%32
    __shared__ float vs[64][65];   // [e][n]
    __shared__ float cs[4][64];    // coef per r for current n-chunk

    const int bh = blockIdx.x;
    const int t  = threadIdx.x;
    const float* kb = K + (size_t)bh * (DH * HW);
    const float* vb = V + (size_t)bh * (DH * HW);

    const int ty = t >> 3;         // 0..31
    const int tx = t & 7;          // 0..7
    const int r  = ty >> 3;        // 0..3   (uniform per warp)
    const int dl = ty & 7;         // d = dl + 8*j  (lane-strided: conflict-free)
    // e = tx + 8*i (lane-strided: conflict-free)

    float acc[8][8];
    float ksa[8];
#pragma unroll
    for (int j = 0; j < 8; j++) {
        ksa[j] = 0.f;
#pragma unroll
        for (int i = 0; i < 8; i++) acc[j][i] = 0.f;
    }

    const int lr = t >> 4;           // load row base 0..15
    const int lc = (t & 15) << 2;    // load col 0..60

    for (int chunk = 0; chunk < 16; chunk++) {
        const int n0 = chunk << 6;
        __syncthreads();
#pragma unroll
        for (int it = 0; it < 4; it++) {
            const int row = lr + (it << 4);
            float4 kv = *(const float4*)(kb + row * HW + n0 + lc);
            ks[row][lc + 0] = fmaxf(kv.x * DNORM, 0.f) + EPS;
            ks[row][lc + 1] = fmaxf(kv.y * DNORM, 0.f) + EPS;
            ks[row][lc + 2] = fmaxf(kv.z * DNORM, 0.f) + EPS;
            ks[row][lc + 3] = fmaxf(kv.w * DNORM, 0.f) + EPS;
            float4 vv = *(const float4*)(vb + row * HW + n0 + lc);
            vs[row][lc + 0] = vv.x;
            vs[row][lc + 1] = vv.y;
            vs[row][lc + 2] = vv.z;
            vs[row][lc + 3] = vv.w;
        }
        if (t < 64) {
            const int n = n0 + t;
            float ch, sh, cw, sw;
            __sincosf((float)(n >> 5) * FREQ, &sh, &ch);
            __sincosf((float)(n & 31) * FREQ, &sw, &cw);
            cs[0][t] = ch * cw;
            cs[1][t] = ch * sw;
            cs[2][t] = sh * cw;
            cs[3][t] = sh * sw;
        }
        __syncthreads();
#pragma unroll 2
        for (int n = 0; n < 64; n++) {
            const float cf = cs[r][n];
            float a[8], bv[8];
#pragma unroll
            for (int j = 0; j < 8; j++) a[j] = ks[dl + (j << 3)][n] * cf;
#pragma unroll
            for (int i = 0; i < 8; i++) bv[i] = vs[tx + (i << 3)][n];
#pragma unroll
            for (int j = 0; j < 8; j++) {
                ksa[j] += a[j];
#pragma unroll
                for (int i = 0; i < 8; i++) acc[j][i] += a[j] * bv[i];
            }
        }
    }

    float* go = g_ctx + (size_t)bh * 256 * CTX_LD;
#pragma unroll
    for (int j = 0; j < 8; j++) {
        const int row = (r << 6) + dl + (j << 3);
#pragma unroll
        for (int i = 0; i < 8; i++)
            go[row * CTX_LD + tx + (i << 3)] = acc[j][i];
        if (tx == 0) go[row * CTX_LD + 64] = ksa[j];   // ksum column
    }
}

// ---------------- Phase 2: out = (Q' ctx) / D  (grid: 8 n-chunks x 256 bh) ----------------
__global__ __launch_bounds__(256, 2)
void p2_kernel(const float* __restrict__ Q, float* __restrict__ O) {
    __shared__ float qs[64][128];  // [d][n-chunk], float4-friendly, conflict-free

    const int bh = blockIdx.y;
    const int n0 = blockIdx.x << 7;       // 128-n chunk
    const int t  = threadIdx.x;
    const int te = t >> 5;                // 0..7 : e = te*8 + i  (warp-uniform)
    const int tn = t & 31;                // n = n0 + tn*4 + jj

    const float* qb  = Q + (size_t)bh * (DH * HW);
    float*       ob  = O + (size_t)bh * (DH * HW);
    const float* ctx = g_ctx + (size_t)bh * 256 * CTX_LD;

#pragma unroll
    for (int it = 0; it < 8; it++) {
        const int row = te + (it << 3);
        float4 qv = *(const float4*)(qb + row * HW + n0 + (tn << 2));
        float4 s;
        s.x = fmaxf(qv.x * DNORM, 0.f) + EPS;
        s.y = fmaxf(qv.y * DNORM, 0.f) + EPS;
        s.z = fmaxf(qv.z * DNORM, 0.f) + EPS;
        s.w = fmaxf(qv.w * DNORM, 0.f) + EPS;
        *(float4*)&qs[row][tn << 2] = s;
    }
    __syncthreads();

    float cf[4][4];
#pragma unroll
    for (int jj = 0; jj < 4; jj++) {
        const int n = n0 + (tn << 2) + jj;
        float ch, sh, cw, sw;
        __sincosf((float)(n >> 5) * FREQ, &sh, &ch);
        __sincosf((float)(n & 31) * FREQ, &sw, &cw);
        cf[0][jj] = ch * cw;
        cf[1][jj] = ch * sw;
        cf[2][jj] = sh * cw;
        cf[3][jj] = sh * sw;
    }

    float acc[8][4];
    float Da[4] = {0.f, 0.f, 0.f, 0.f};
#pragma unroll
    for (int i = 0; i < 8; i++)
#pragma unroll
        for (int jj = 0; jj < 4; jj++) acc[i][jj] = 0.f;

#pragma unroll
    for (int r = 0; r < 4; r++) {
        const float c0f = cf[r][0], c1f = cf[r][1], c2f = cf[r][2], c3f = cf[r][3];
        const float* crow = ctx + (size_t)(r << 6) * CTX_LD;
#pragma unroll 4
        for (int d = 0; d < 64; d++) {
            float4 a4 = *(const float4*)&qs[(r << 6) ? ((r << 6) + d - (r << 6)) : d][tn << 2]; // d row
            // (index is just d; written plainly below to avoid confusion)
            a4 = *(const float4*)&qs[d][tn << 2];
            const float ap0 = a4.x * c0f;
            const float ap1 = a4.y * c1f;
            const float ap2 = a4.z * c2f;
            const float ap3 = a4.w * c3f;
            const float4 cA = *(const float4*)(crow + (te << 3));
            const float4 cB = *(const float4*)(crow + (te << 3) + 4);
            const float ksv = crow[64];
            const float cc[8] = {cA.x, cA.y, cA.z, cA.w, cB.x, cB.y, cB.z, cB.w};
#pragma unroll
            for (int i = 0; i < 8; i++) {
                acc[i][0] += cc[i] * ap0;
                acc[i][1] += cc[i] * ap1;
                acc[i][2] += cc[i] * ap2;
                acc[i][3] += cc[i] * ap3;
            }
            Da[0] += ksv * ap0;
            Da[1] += ksv * ap1;
            Da[2] += ksv * ap2;
            Da[3] += ksv * ap3;
            crow += CTX_LD;
        }
    }

    float rin[4];
#pragma unroll
    for (int jj = 0; jj < 4; jj++) rin[jj] = 1.0f / Da[jj];
#pragma unroll
    for (int i = 0; i < 8; i++) {
        float4 o;
        o.x = acc[i][0] * rin[0];
        o.y = acc[i][1] * rin[1];
        o.z = acc[i][2] * rin[2];
        o.w = acc[i][3] * rin[3];
        *(float4*)(ob + (size_t)((te << 3) + i) * HW + n0 + (tn << 2)) = o;
    }
}

extern "C" void kernel_launch(void* const* d_in, const int* in_sizes, int n_in,
                              void* d_out, int out_size) {
    (void)in_sizes; (void)n_in; (void)out_size;
    const float* q = (const float*)d_in[0];
    const float* k = (const float*)d_in[1];
    const float* v = (const float*)d_in[2];
    float* o = (float*)d_out;

    p1_kernel<<<NBH, 256>>>(k, v);
    p2_kernel<<<dim3(8, NBH), 256>>>(q, o);
}

// round 13
// speedup vs baseline: 1.1916x; 1.1862x over previous
#include <cuda_runtime.h>
#include <cstdint>
#include <cstddef>

// CosAttn2d: B=32, C=512, H=W=32, n_head=8, M=48
// Phase 1: ctx[k'=r*64+d][e] = sum_n coef_r[n]*ka[d,n]*v[e,n]; col 64 = ksum
// Phase 2: out[e,n] = (sum_{k'} coef*qa * ctx[k'][e]) / (sum_{k'} coef*qa * ksum[k'])
// This round: packed f32x2 (FFMA2) inner loops -> 2x fma-pipe throughput.

#define HW      1024
#define DH      64
#define NBH     256
#define FREQ    0.0327249234748937f   // pi/96
#define DNORM   0.2102241038134286f   // 512^-0.25
#define EPS     1e-5f
#define CTX_LD  68

typedef unsigned long long ull;

__device__ float g_ctx[NBH * 256 * CTX_LD];   // 17.8 MB scratch

__device__ __forceinline__ ull pk2(float lo, float hi) {
    ull r; asm("mov.b64 %0, {%1, %2};" : "=l"(r) : "f"(lo), "f"(hi)); return r;
}
__device__ __forceinline__ void upk2(ull v, float& lo, float& hi) {
    asm("mov.b64 {%0, %1}, %2;" : "=f"(lo), "=f"(hi) : "l"(v));
}
__device__ __forceinline__ ull mul2(ull a, ull b) {
    ull r; asm("mul.rn.f32x2 %0, %1, %2;" : "=l"(r) : "l"(a), "l"(b)); return r;
}
__device__ __forceinline__ ull add2(ull a, ull b) {
    ull r; asm("add.rn.f32x2 %0, %1, %2;" : "=l"(r) : "l"(a), "l"(b)); return r;
}
__device__ __forceinline__ void fma2(ull& d, ull a, ull b) {
    asm("fma.rn.f32x2 %0, %1, %2, %3;" : "=l"(d) : "l"(a), "l"(b), "l"(d));
}

// ---------------- Phase 1: ctx = K'^T V (one block per bh) ----------------
// Thread (r from warp, dl, tx): d-pairs {2dl+16jp, +1}, e = tx+8i
__global__ __launch_bounds__(256, 2)
void p1_kernel(const float* __restrict__ K, const float* __restrict__ V) {
    __shared__ float ks_t[64][66];   // [n][d]  (transposed, d contiguous)
    __shared__ float vs_t[64][66];   // [n][e]
    __shared__ float cs[4][64];

    const int bh = blockIdx.x;
    const int t  = threadIdx.x;
    const float* kb = K + (size_t)bh * (DH * HW);
    const float* vb = V + (size_t)bh * (DH * HW);

    const int ty = t >> 3;           // 0..31
    const int tx = t & 7;            // 0..7
    const int r  = ty >> 3;          // 0..3 (uniform per warp)
    const int dl = ty & 7;           // 0..7

    ull acc2[4][8];
    ull ksa2[4];
#pragma unroll
    for (int jp = 0; jp < 4; jp++) {
        ksa2[jp] = 0ull;
#pragma unroll
        for (int i = 0; i < 8; i++) acc2[jp][i] = 0ull;
    }

    const int lr = t >> 4;           // 0..15 (gmem row base)
    const int lc = (t & 15) << 2;    // 0..60 (n col)

    for (int chunk = 0; chunk < 16; chunk++) {
        const int n0 = chunk << 6;
        __syncthreads();
#pragma unroll
        for (int it = 0; it < 4; it++) {
            const int row = lr + (it << 4);
            float4 kv = *(const float4*)(kb + row * HW + n0 + lc);
            ks_t[lc + 0][row] = fmaxf(kv.x * DNORM, 0.f) + EPS;
            ks_t[lc + 1][row] = fmaxf(kv.y * DNORM, 0.f) + EPS;
            ks_t[lc + 2][row] = fmaxf(kv.z * DNORM, 0.f) + EPS;
            ks_t[lc + 3][row] = fmaxf(kv.w * DNORM, 0.f) + EPS;
            float4 vv = *(const float4*)(vb + row * HW + n0 + lc);
            vs_t[lc + 0][row] = vv.x;
            vs_t[lc + 1][row] = vv.y;
            vs_t[lc + 2][row] = vv.z;
            vs_t[lc + 3][row] = vv.w;
        }
        if (t < 64) {
            const int n = n0 + t;
            float ch, sh, cw, sw;
            __sincosf((float)(n >> 5) * FREQ, &sh, &ch);
            __sincosf((float)(n & 31) * FREQ, &sw, &cw);
            cs[0][t] = ch * cw;
            cs[1][t] = ch * sw;
            cs[2][t] = sh * cw;
            cs[3][t] = sh * sw;
        }
        __syncthreads();

#pragma unroll 2
        for (int n = 0; n < 64; n++) {
            const float cfv = cs[r][n];
            const ull cf2 = pk2(cfv, cfv);
            const ull* ksp = (const ull*)&ks_t[n][0];
            ull ksc[4];
#pragma unroll
            for (int jp = 0; jp < 4; jp++) {
                ull k2 = ksp[dl + (jp << 3)];      // d pair {2dl+16jp, +1}
                ksc[jp] = mul2(k2, cf2);
                ksa2[jp] = add2(ksa2[jp], ksc[jp]);
            }
            ull bvd[8];
#pragma unroll
            for (int i = 0; i < 8; i++) {
                float b = vs_t[n][tx + (i << 3)];
                bvd[i] = pk2(b, b);
            }
#pragma unroll
            for (int jp = 0; jp < 4; jp++)
#pragma unroll
                for (int i = 0; i < 8; i++)
                    fma2(acc2[jp][i], ksc[jp], bvd[i]);
        }
    }

    float* go = g_ctx + (size_t)bh * 256 * CTX_LD;
#pragma unroll
    for (int jp = 0; jp < 4; jp++) {
        const int d0 = (dl << 1) + (jp << 4);
        float* r0 = go + (size_t)((r << 6) + d0) * CTX_LD;
        float* r1 = r0 + CTX_LD;
#pragma unroll
        for (int i = 0; i < 8; i++) {
            float a, b;
            upk2(acc2[jp][i], a, b);
            r0[tx + (i << 3)] = a;
            r1[tx + (i << 3)] = b;
        }
        if (tx == 0) {
            float a, b;
            upk2(ksa2[jp], a, b);
            r0[64] = a;
            r1[64] = b;
        }
    }
}

// ---------------- Phase 2: out = (Q' ctx) / D  (grid: 8 n-chunks x 256 bh) ----------------
__global__ __launch_bounds__(256, 2)
void p2_kernel(const float* __restrict__ Q, float* __restrict__ O) {
    __shared__ ull qs2[64][66];       // [d][n-pair], 4 floats per thread as 2 packed pairs

    const int bh = blockIdx.y;
    const int n0 = blockIdx.x << 7;   // 128-n chunk
    const int t  = threadIdx.x;
    const int te = t >> 5;            // 0..7 : e = te*8 + i (warp-uniform)
    const int tn = t & 31;            // n = n0 + tn*4 + jj

    const float* qb  = Q + (size_t)bh * (DH * HW);
    float*       ob  = O + (size_t)bh * (DH * HW);
    const float* ctx = g_ctx + (size_t)bh * 256 * CTX_LD;

#pragma unroll
    for (int it = 0; it < 8; it++) {
        const int row = te + (it << 3);
        float4 qv = *(const float4*)(qb + row * HW + n0 + (tn << 2));
        float4 s;
        s.x = fmaxf(qv.x * DNORM, 0.f) + EPS;
        s.y = fmaxf(qv.y * DNORM, 0.f) + EPS;
        s.z = fmaxf(qv.z * DNORM, 0.f) + EPS;
        s.w = fmaxf(qv.w * DNORM, 0.f) + EPS;
        *(float4*)((char*)&qs2[row][0] + (tn << 4)) = s;
    }
    __syncthreads();

    // coefficient pairs for this thread's 4 n values
    ull cf2a[4], cf2b[4];
    {
        float cf[4][4];
#pragma unroll
        for (int jj = 0; jj < 4; jj++) {
            const int n = n0 + (tn << 2) + jj;
            float ch, sh, cw, sw;
            __sincosf((float)(n >> 5) * FREQ, &sh, &ch);
            __sincosf((float)(n & 31) * FREQ, &sw, &cw);
            cf[0][jj] = ch * cw;
            cf[1][jj] = ch * sw;
            cf[2][jj] = sh * cw;
            cf[3][jj] = sh * sw;
        }
#pragma unroll
        for (int rr = 0; rr < 4; rr++) {
            cf2a[rr] = pk2(cf[rr][0], cf[rr][1]);
            cf2b[rr] = pk2(cf[rr][2], cf[rr][3]);
        }
    }

    ull acc2[8][2];
    ull Da0 = 0ull, Da1 = 0ull;
#pragma unroll
    for (int i = 0; i < 8; i++) { acc2[i][0] = 0ull; acc2[i][1] = 0ull; }

#pragma unroll
    for (int r = 0; r < 4; r++) {
        const float* crow = ctx + (size_t)(r << 6) * CTX_LD;
#pragma unroll 4
        for (int d = 0; d < 64; d++) {
            ulonglong2 q2 = *(const ulonglong2*)((const char*)&qs2[d][0] + (tn << 4));
            const ull ap0 = mul2(q2.x, cf2a[r]);   // (n jj=0,1)
            const ull ap1 = mul2(q2.y, cf2b[r]);   // (n jj=2,3)

            const float4 cA = *(const float4*)(crow + (te << 3));
            const float4 cB = *(const float4*)(crow + (te << 3) + 4);
            const float ksv = crow[64];
            const ull ksd = pk2(ksv, ksv);
            fma2(Da0, ksd, ap0);
            fma2(Da1, ksd, ap1);

            const float cc[8] = {cA.x, cA.y, cA.z, cA.w, cB.x, cB.y, cB.z, cB.w};
#pragma unroll
            for (int i = 0; i < 8; i++) {
                const ull cd = pk2(cc[i], cc[i]);
                fma2(acc2[i][0], cd, ap0);
                fma2(acc2[i][1], cd, ap1);
            }
            crow += CTX_LD;
        }
    }

    float D0, D1, D2, D3;
    upk2(Da0, D0, D1);
    upk2(Da1, D2, D3);
    const float ri0 = 1.0f / D0, ri1 = 1.0f / D1, ri2 = 1.0f / D2, ri3 = 1.0f / D3;

#pragma unroll
    for (int i = 0; i < 8; i++) {
        float o0, o1, o2, o3;
        upk2(acc2[i][0], o0, o1);
        upk2(acc2[i][1], o2, o3);
        float4 o;
        o.x = o0 * ri0;
        o.y = o1 * ri1;
        o.z = o2 * ri2;
        o.w = o3 * ri3;
        *(float4*)(ob + (size_t)((te << 3) + i) * HW + n0 + (tn << 2)) = o;
    }
}

extern "C" void kernel_launch(void* const* d_in, const int* in_sizes, int n_in,
                              void* d_out, int out_size) {
    (void)in_sizes; (void)n_in; (void)out_size;
    const float* q = (const float*)d_in[0];
    const float* k = (const float*)d_in[1];
    const float* v = (const float*)d_in[2];
    float* o = (float*)d_out;

    p1_kernel<<<NBH, 256>>>(k, v);
    p2_kernel<<<dim3(8, NBH), 256>>>(q, o);
}

// round 14
// speedup vs baseline: 1.2411x; 1.0415x over previous
#include <cuda_runtime.h>
#include <cstdint>
#include <cstddef>

// CosAttn2d fused: B=32, C=512, H=W=32, n_head=8, M=48
// One block per bh. Phase 1: ctx[k'=r*64+d][e] = sum_n coef_r[n]*ka[d,n]*v[e,n]
// (col 64 = ksum) accumulated in registers, stored to SMEM.
// Phase 2: out[e,n] = (sum_k' coef*qa*ctx[k'][e]) / (sum_k' coef*qa*ksum[k'])
// reading ctx from SMEM (uniform broadcast), packed f32x2 math throughout.

#define HW      1024
#define DH      64
#define NBH     256
#define FREQ    0.0327249234748937f   // pi/96
#define DNORM   0.2102241038134286f   // 512^-0.25
#define EPS     1e-5f
#define CTX_LD  68                    // floats per ctx row (16B-aligned rows)

typedef unsigned long long ull;

// ---- dynamic smem layout ----
// [0, 69632)            : ctx_s[256][68]  (float)
// [69632, 103424)       : union { ks_t[64][66] + vs_t[64][66] (float) | qs2[64][66] (ull) }
// [103424, 104448)      : cs[4][64] (float)
#define SMEM_CTX_BYTES   (256 * CTX_LD * 4)
#define SMEM_TILE_BYTES  (64 * 66 * 8)
#define SMEM_BYTES       (SMEM_CTX_BYTES + SMEM_TILE_BYTES + 4 * 64 * 4)

__device__ __forceinline__ ull pk2(float lo, float hi) {
    ull r; asm("mov.b64 %0, {%1, %2};" : "=l"(r) : "f"(lo), "f"(hi)); return r;
}
__device__ __forceinline__ void upk2(ull v, float& lo, float& hi) {
    asm("mov.b64 {%0, %1}, %2;" : "=f"(lo), "=f"(hi) : "l"(v));
}
__device__ __forceinline__ ull mul2(ull a, ull b) {
    ull r; asm("mul.rn.f32x2 %0, %1, %2;" : "=l"(r) : "l"(a), "l"(b)); return r;
}
__device__ __forceinline__ ull add2(ull a, ull b) {
    ull r; asm("add.rn.f32x2 %0, %1, %2;" : "=l"(r) : "l"(a), "l"(b)); return r;
}
__device__ __forceinline__ void fma2(ull& d, ull a, ull b) {
    asm("fma.rn.f32x2 %0, %1, %2, %3;" : "=l"(d) : "l"(a), "l"(b), "l"(d));
}

__global__ __launch_bounds__(256, 2)
void fused_kernel(const float* __restrict__ Q, const float* __restrict__ K,
                  const float* __restrict__ V, float* __restrict__ O) {
    extern __shared__ char smem_raw[];
    float (*ctx_s)[CTX_LD] = (float(*)[CTX_LD])smem_raw;
    float (*ks_t)[66] = (float(*)[66])(smem_raw + SMEM_CTX_BYTES);
    float (*vs_t)[66] = (float(*)[66])(smem_raw + SMEM_CTX_BYTES + 64 * 66 * 4);
    ull   (*qs2)[66]  = (ull(*)[66])(smem_raw + SMEM_CTX_BYTES);
    float (*cs)[64]   = (float(*)[64])(smem_raw + SMEM_CTX_BYTES + SMEM_TILE_BYTES);

    const int bh = blockIdx.x;
    const int t  = threadIdx.x;
    const float* qb = Q + (size_t)bh * (DH * HW);
    const float* kb = K + (size_t)bh * (DH * HW);
    const float* vb = V + (size_t)bh * (DH * HW);
    float*       ob = O + (size_t)bh * (DH * HW);

    // ================= Phase 1: ctx = K'^T V =================
    {
        const int ty = t >> 3;           // 0..31
        const int tx = t & 7;            // 0..7  (e = tx + 8i)
        const int r  = ty >> 3;          // 0..3  (uniform per warp)
        const int dl = ty & 7;           // d-pairs {2dl+16jp, +1}

        ull acc2[4][8];
        ull ksa2[4];
#pragma unroll
        for (int jp = 0; jp < 4; jp++) {
            ksa2[jp] = 0ull;
#pragma unroll
            for (int i = 0; i < 8; i++) acc2[jp][i] = 0ull;
        }

        const int lr = t >> 4;           // 0..15 (gmem row base)
        const int lc = (t & 15) << 2;    // 0..60 (n col)

        for (int chunk = 0; chunk < 16; chunk++) {
            const int n0 = chunk << 6;
            __syncthreads();
#pragma unroll
            for (int it = 0; it < 4; it++) {
                const int row = lr + (it << 4);
                float4 kv = *(const float4*)(kb + row * HW + n0 + lc);
                ks_t[lc + 0][row] = fmaxf(kv.x * DNORM, 0.f) + EPS;
                ks_t[lc + 1][row] = fmaxf(kv.y * DNORM, 0.f) + EPS;
                ks_t[lc + 2][row] = fmaxf(kv.z * DNORM, 0.f) + EPS;
                ks_t[lc + 3][row] = fmaxf(kv.w * DNORM, 0.f) + EPS;
                float4 vv = *(const float4*)(vb + row * HW + n0 + lc);
                vs_t[lc + 0][row] = vv.x;
                vs_t[lc + 1][row] = vv.y;
                vs_t[lc + 2][row] = vv.z;
                vs_t[lc + 3][row] = vv.w;
            }
            if (t < 64) {
                const int n = n0 + t;
                float ch, sh, cw, sw;
                __sincosf((float)(n >> 5) * FREQ, &sh, &ch);
                __sincosf((float)(n & 31) * FREQ, &sw, &cw);
                cs[0][t] = ch * cw;
                cs[1][t] = ch * sw;
                cs[2][t] = sh * cw;
                cs[3][t] = sh * sw;
            }
            __syncthreads();

#pragma unroll 2
            for (int n = 0; n < 64; n++) {
                const float cfv = cs[r][n];
                const ull cf2 = pk2(cfv, cfv);
                const ull* ksp = (const ull*)&ks_t[n][0];
                ull ksc[4];
#pragma unroll
                for (int jp = 0; jp < 4; jp++) {
                    ull k2 = ksp[dl + (jp << 3)];
                    ksc[jp] = mul2(k2, cf2);
                    ksa2[jp] = add2(ksa2[jp], ksc[jp]);
                }
                ull bvd[8];
#pragma unroll
                for (int i = 0; i < 8; i++) {
                    float b = vs_t[n][tx + (i << 3)];
                    bvd[i] = pk2(b, b);
                }
#pragma unroll
                for (int jp = 0; jp < 4; jp++)
#pragma unroll
                    for (int i = 0; i < 8; i++)
                        fma2(acc2[jp][i], ksc[jp], bvd[i]);
            }
        }

        // write ctx to smem (ctx region untouched by tiles; no sync needed yet)
#pragma unroll
        for (int jp = 0; jp < 4; jp++) {
            const int d0 = (dl << 1) + (jp << 4);
            float* r0 = &ctx_s[(r << 6) + d0][0];
            float* r1 = r0 + CTX_LD;
#pragma unroll
            for (int i = 0; i < 8; i++) {
                float a, b;
                upk2(acc2[jp][i], a, b);
                r0[tx + (i << 3)] = a;
                r1[tx + (i << 3)] = b;
            }
            if (tx == 0) {
                float a, b;
                upk2(ksa2[jp], a, b);
                r0[64] = a;
                r1[64] = b;
            }
        }
    }

    // ================= Phase 2: out = (Q' ctx) / D =================
    {
        const int te = t >> 5;            // 0..7 : e = te*8 + i (warp-uniform)
        const int tn = t & 31;            // n = n0 + tn*4 + jj

        for (int chunk = 0; chunk < 8; chunk++) {
            const int n0 = chunk << 7;
            __syncthreads();              // ctx ready (chunk 0) / prior qs2 reads done
#pragma unroll
            for (int it = 0; it < 8; it++) {
                const int row = te + (it << 3);
                float4 qv = *(const float4*)(qb + row * HW + n0 + (tn << 2));
                float4 s;
                s.x = fmaxf(qv.x * DNORM, 0.f) + EPS;
                s.y = fmaxf(qv.y * DNORM, 0.f) + EPS;
                s.z = fmaxf(qv.z * DNORM, 0.f) + EPS;
                s.w = fmaxf(qv.w * DNORM, 0.f) + EPS;
                *(float4*)((char*)&qs2[row][0] + (tn << 4)) = s;
            }
            __syncthreads();

            ull cf2a[4], cf2b[4];
            {
                float cf[4][4];
#pragma unroll
                for (int jj = 0; jj < 4; jj++) {
                    const int n = n0 + (tn << 2) + jj;
                    float ch, sh, cw, sw;
                    __sincosf((float)(n >> 5) * FREQ, &sh, &ch);
                    __sincosf((float)(n & 31) * FREQ, &sw, &cw);
                    cf[0][jj] = ch * cw;
                    cf[1][jj] = ch * sw;
                    cf[2][jj] = sh * cw;
                    cf[3][jj] = sh * sw;
                }
#pragma unroll
                for (int rr = 0; rr < 4; rr++) {
                    cf2a[rr] = pk2(cf[rr][0], cf[rr][1]);
                    cf2b[rr] = pk2(cf[rr][2], cf[rr][3]);
                }
            }

            ull acc2[8][2];
            ull Da0 = 0ull, Da1 = 0ull;
#pragma unroll
            for (int i = 0; i < 8; i++) { acc2[i][0] = 0ull; acc2[i][1] = 0ull; }

#pragma unroll
            for (int r = 0; r < 4; r++) {
                const float* crow = &ctx_s[r << 6][0];
#pragma unroll 4
                for (int d = 0; d < 64; d++) {
                    ulonglong2 q2 = *(const ulonglong2*)((const char*)&qs2[d][0] + (tn << 4));
                    const ull ap0 = mul2(q2.x, cf2a[r]);   // n jj=0,1
                    const ull ap1 = mul2(q2.y, cf2b[r]);   // n jj=2,3

                    const float4 cA = *(const float4*)(crow + (te << 3));      // uniform LDS
                    const float4 cB = *(const float4*)(crow + (te << 3) + 4);  // broadcast
                    const float ksv = crow[64];
                    const ull ksd = pk2(ksv, ksv);
                    fma2(Da0, ksd, ap0);
                    fma2(Da1, ksd, ap1);

                    const float cc[8] = {cA.x, cA.y, cA.z, cA.w, cB.x, cB.y, cB.z, cB.w};
#pragma unroll
                    for (int i = 0; i < 8; i++) {
                        const ull cd = pk2(cc[i], cc[i]);
                        fma2(acc2[i][0], cd, ap0);
                        fma2(acc2[i][1], cd, ap1);
                    }
                    crow += CTX_LD;
                }
            }

            float D0, D1, D2, D3;
            upk2(Da0, D0, D1);
            upk2(Da1, D2, D3);
            const float ri0 = 1.0f / D0, ri1 = 1.0f / D1;
            const float ri2 = 1.0f / D2, ri3 = 1.0f / D3;

#pragma unroll
            for (int i = 0; i < 8; i++) {
                float o0, o1, o2, o3;
                upk2(acc2[i][0], o0, o1);
                upk2(acc2[i][1], o2, o3);
                float4 o;
                o.x = o0 * ri0;
                o.y = o1 * ri1;
                o.z = o2 * ri2;
                o.w = o3 * ri3;
                *(float4*)(ob + (size_t)((te << 3) + i) * HW + n0 + (tn << 2)) = o;
            }
        }
    }
}

extern "C" void kernel_launch(void* const* d_in, const int* in_sizes, int n_in,
                              void* d_out, int out_size) {
    (void)in_sizes; (void)n_in; (void)out_size;
    const float* q = (const float*)d_in[0];
    const float* k = (const float*)d_in[1];
    const float* v = (const float*)d_in[2];
    float* o = (float*)d_out;

    cudaFuncSetAttribute(fused_kernel,
                         cudaFuncAttributeMaxDynamicSharedMemorySize, SMEM_BYTES);
    fused_kernel<<<NBH, 256, SMEM_BYTES>>>(q, k, v, o);
}